// round 16
// baseline (speedup 1.0000x reference)
#include <cuda_runtime.h>
#include <cuda_fp16.h>
#include <cstdint>

#define DIMC   1024
#define NHEAD  16
#define HDIM   64
#define BATCH  2
#define MAXT   2048
#define MAXM   (BATCH * MAXT)

// q scale folded into Q at QKV epilogue: 1/sqrt(64) * log2(e)
#define QSCALE (0.125f * 1.4426950408889634f)

// Packed-tile geometry: A block = 128 rows x 32 k (fp16, 64B rows, swizzled) = 8KB
//                       B block = 256 rows x 32 k = 16KB
#define ABLKB 8192
#define BBLKB 16384

// Scratch (__device__ globals; no cudaMalloc allowed). 128B-aligned for bulk DMA.
__device__ __align__(128) __half g_xA[(size_t)MAXM * DIMC];        // packed A (QKV)
__device__ __align__(128) __half g_wqkvB[(size_t)3 * DIMC * DIMC]; // packed B (QKV)
__device__ __align__(128) __half g_wprojB[(size_t)DIMC * DIMC];    // packed B (proj)
__device__ __align__(128) __half g_qkv[(size_t)MAXM * 3 * DIMC];   // row-major (attn in)
__device__ __align__(128) __half g_attnP[(size_t)MAXM * DIMC];     // packed A (proj)

// ---------------------------------------------------------------------------
// helpers
// ---------------------------------------------------------------------------
__device__ __forceinline__ uint32_t smem_u32(const void* p) {
    uint32_t a;
    asm("{ .reg .u64 t; cvta.to.shared.u64 t, %1; cvt.u32.u64 %0, t; }" : "=r"(a) : "l"(p));
    return a;
}

#define CP_ASYNC16(dst_u32, src_ptr) \
    asm volatile("cp.async.cg.shared.global [%0], [%1], 16;" \
                 :: "r"(dst_u32), "l"(src_ptr) : "memory")
#define CP_COMMIT()  asm volatile("cp.async.commit_group;" ::: "memory")
#define CP_WAIT(n)   asm volatile("cp.async.wait_group %0;" :: "n"(n) : "memory")

#define CP_BULK(dst_u32, src_ptr, nbytes, mbar_u32) \
    asm volatile("cp.async.bulk.shared::cluster.global.mbarrier::complete_tx::bytes " \
                 "[%0], [%1], %2, [%3];" \
                 :: "r"(dst_u32), "l"(src_ptr), "r"(nbytes), "r"(mbar_u32) : "memory")

#define MBARRIER_INIT(addr, cnt) \
    asm volatile("mbarrier.init.shared.b64 [%0], %1;" :: "r"(addr), "r"(cnt) : "memory")
#define MBARRIER_EXPECT_TX(addr, tx) \
    asm volatile("mbarrier.arrive.expect_tx.shared.b64 _, [%0], %1;" \
                 :: "r"(addr), "r"(tx) : "memory")
#define MBARRIER_WAIT_PARITY(addr, par) do {                                        \
    uint32_t _m = (addr), _p = (par), _d;                                           \
    asm volatile("{\n\t.reg .pred p;\n\t"                                           \
        "mbarrier.try_wait.parity.acquire.cta.shared::cta.b64 p, [%1], %2;\n\t"     \
        "selp.b32 %0, 1, 0, p;\n\t}" : "=r"(_d) : "r"(_m), "r"(_p) : "memory");     \
    if (!_d) {                                                                      \
        asm volatile("{\n\t.reg .pred P1;\n\tWL_%=:\n\t"                            \
            "mbarrier.try_wait.parity.acquire.cta.shared::cta.b64 P1, [%0], %1, 0x989680;\n\t" \
            "@P1 bra.uni WD_%=;\n\tbra.uni WL_%=;\n\tWD_%=:\n\t}"                   \
            :: "r"(_m), "r"(_p) : "memory");                                        \
    }                                                                               \
} while (0)

__device__ __forceinline__ void mma_f16(float* d, const unsigned* a,
                                        unsigned b0, unsigned b1) {
    asm volatile(
        "mma.sync.aligned.m16n8k16.row.col.f32.f16.f16.f32 "
        "{%0,%1,%2,%3}, {%4,%5,%6,%7}, {%8,%9}, {%0,%1,%2,%3};\n"
        : "+f"(d[0]), "+f"(d[1]), "+f"(d[2]), "+f"(d[3])
        : "r"(a[0]), "r"(a[1]), "r"(a[2]), "r"(a[3]), "r"(b0), "r"(b1));
}

__device__ __forceinline__ void ldmx4(unsigned* r, uint32_t addr) {
    asm volatile("ldmatrix.sync.aligned.m8n8.x4.shared.b16 {%0,%1,%2,%3}, [%4];"
                 : "=r"(r[0]), "=r"(r[1]), "=r"(r[2]), "=r"(r[3]) : "r"(addr));
}
__device__ __forceinline__ void ldmx4t(unsigned* r, uint32_t addr) {
    asm volatile("ldmatrix.sync.aligned.m8n8.x4.trans.shared.b16 {%0,%1,%2,%3}, [%4];"
                 : "=r"(r[0]), "=r"(r[1]), "=r"(r[2]), "=r"(r[3]) : "r"(addr));
}

__device__ __forceinline__ unsigned pack2(float x, float y) {
    __half2 h = __floats2half2_rn(x, y);
    return *reinterpret_cast<unsigned*>(&h);
}
__device__ __forceinline__ float ex2f(float x) {
    float y;
    asm("ex2.approx.f32 %0, %1;" : "=f"(y) : "f"(x));
    return y;
}

// ---------------------------------------------------------------------------
// Packers: write (row, col) at row*64 + (col_bytes ^ xorv(row)),
// xorv(row) = ((row>>1)&3)<<4 — XOR only touches byte-bits 4..5.
// ---------------------------------------------------------------------------
__global__ __launch_bounds__(256) void xpack_kernel(const float* __restrict__ x) {
    const int kc = blockIdx.x, mb = blockIdx.y;
    const int tid = threadIdx.x;
    const int r = tid >> 1, hf = tid & 1;
    const float* src = x + (size_t)(mb * 128 + r) * DIMC + kc * 32 + hf * 16;
    float4 v0 = *reinterpret_cast<const float4*>(src);
    float4 v1 = *reinterpret_cast<const float4*>(src + 4);
    float4 v2 = *reinterpret_cast<const float4*>(src + 8);
    float4 v3 = *reinterpret_cast<const float4*>(src + 12);
    uint4 u0 = make_uint4(pack2(v0.x, v0.y), pack2(v0.z, v0.w),
                          pack2(v1.x, v1.y), pack2(v1.z, v1.w));
    uint4 u1 = make_uint4(pack2(v2.x, v2.y), pack2(v2.z, v2.w),
                          pack2(v3.x, v3.y), pack2(v3.z, v3.w));
    const uint32_t xorv = ((r >> 1) & 3) << 4;
    char* dst = (char*)g_xA + (size_t)(mb * 32 + kc) * ABLKB + r * 64;
    *reinterpret_cast<uint4*>(dst + ((hf * 32)      ^ xorv)) = u0;
    *reinterpret_cast<uint4*>(dst + ((hf * 32 + 16) ^ xorv)) = u1;
}

// W fp32 [1024,N] -> packed B [nb][kc][256x32 f16 swizzled], rows = n, cols = k
__global__ __launch_bounds__(256) void wpack_kernel(const float* __restrict__ W,
                                                    __half* __restrict__ out, int N) {
    const int nb = blockIdx.x, kc = blockIdx.y;
    const int n = threadIdx.x;
    __half h[32];
    #pragma unroll
    for (int k = 0; k < 32; k++)
        h[k] = __float2half_rn(W[(size_t)(kc * 32 + k) * N + nb * 256 + n]);
    const uint32_t xorv = ((n >> 1) & 3) << 4;
    char* dst = (char*)out + (size_t)(nb * 32 + kc) * BBLKB + n * 64;
    const uint4* hu = reinterpret_cast<const uint4*>(h);
    #pragma unroll
    for (int u = 0; u < 4; u++)
        *reinterpret_cast<uint4*>(dst + ((u * 16) ^ xorv)) = hu[u];
}

// ---------------------------------------------------------------------------
// Bulk-DMA fp16 GEMM + bias: 128(M) x 256(N) CTA tile, 8 warps (64x64 warp
// tiles), BK=32, 6-buffer ring fed by cp.async.bulk (2 copies/chunk, thread 0)
// + mbarrier. Fragments via ldmatrix; addr = base + row*64 + (col ^ xorv(row)).
// ---------------------------------------------------------------------------
#define STAGEB   (ABLKB + BBLKB)       // 24576
#define NBUF     6
#define MBAR_OFF (NBUF * STAGEB)       // 147456
#define G_SMEM   (MBAR_OFF + 64)       // 147520

__global__ __launch_bounds__(256, 1) void gemm_bulk_kernel(
    const __half* __restrict__ Apack, const __half* __restrict__ Bpack,
    const float* __restrict__ bias, void* __restrict__ Cout,
    int N, int half_out, int q_cols)
{
    extern __shared__ char smraw[];
    const uint32_t s0 = smem_u32(smraw);

    const int tid  = threadIdx.x;
    const int lane = tid & 31;
    const int warp = tid >> 5;
    const int wr = (warp >> 2) * 64;
    const int wc = (warp & 3) * 64;
    const int mb = blockIdx.y, nb = blockIdx.x;
    const int row0 = mb * 128, col0 = nb * 256;

    if (tid == 0) {
        #pragma unroll
        for (int s = 0; s < NBUF; s++) MBARRIER_INIT(s0 + MBAR_OFF + 8 * s, 1);
    }
    __syncthreads();

    float acc[4][8][4];
    #pragma unroll
    for (int mt = 0; mt < 4; mt++)
        #pragma unroll
        for (int nt = 0; nt < 8; nt++)
            #pragma unroll
            for (int i = 0; i < 4; i++) acc[mt][nt][i] = 0.f;

    const char* Abase = (const char*)Apack + (size_t)mb * 32 * ABLKB;
    const char* Bbase = (const char*)Bpack + (size_t)nb * 32 * BBLKB;

    auto stage = [&](int kc) {
        const int buf = kc % NBUF;
        const uint32_t mbar = s0 + MBAR_OFF + 8 * buf;
        const uint32_t dst  = s0 + buf * STAGEB;
        MBARRIER_EXPECT_TX(mbar, STAGEB);
        CP_BULK(dst,         Abase + (size_t)kc * ABLKB, ABLKB, mbar);
        CP_BULK(dst + ABLKB, Bbase + (size_t)kc * BBLKB, BBLKB, mbar);
    };

    // fragment addressing: rowbase (row*64) and xor held separately
    const int f_row = lane & 15;
    const uint32_t cb = (lane >> 4) << 4;   // 0 or 16 bytes
    uint32_t rbA[4], xvA[4], rbB[4], xvB[4];
    #pragma unroll
    for (int i = 0; i < 4; i++) {
        const int rA = wr + i * 16 + f_row;
        const int rB = wc + i * 16 + f_row;
        rbA[i] = rA * 64;          xvA[i] = ((rA >> 1) & 3) << 4;
        rbB[i] = ABLKB + rB * 64;  xvB[i] = ((rB >> 1) & 3) << 4;
    }

    auto compute = [&](uint32_t base) {
        #pragma unroll
        for (int ks = 0; ks < 2; ks++) {
            const uint32_t col = ks * 32 + cb;
            unsigned af[4][4], bf[4][4];
            #pragma unroll
            for (int mt = 0; mt < 4; mt++)
                ldmx4(af[mt], base + rbA[mt] + (col ^ xvA[mt]));
            #pragma unroll
            for (int ntp = 0; ntp < 4; ntp++)
                ldmx4(bf[ntp], base + rbB[ntp] + (col ^ xvB[ntp]));
            #pragma unroll
            for (int mt = 0; mt < 4; mt++)
                #pragma unroll
                for (int ntp = 0; ntp < 4; ntp++) {
                    mma_f16(acc[mt][2 * ntp],     af[mt], bf[ntp][0], bf[ntp][2]);
                    mma_f16(acc[mt][2 * ntp + 1], af[mt], bf[ntp][1], bf[ntp][3]);
                }
        }
    };

    if (tid == 0) { stage(0); stage(1); stage(2); stage(3); }

    int par[NBUF] = {0, 0, 0, 0, 0, 0};
    for (int i = 0; i < 32; i += 2) {
        const int b0 = i % NBUF, b1 = (i + 1) % NBUF;
        MBARRIER_WAIT_PARITY(s0 + MBAR_OFF + 8 * b0, par[b0]); par[b0] ^= 1;
        MBARRIER_WAIT_PARITY(s0 + MBAR_OFF + 8 * b1, par[b1]); par[b1] ^= 1;
        __syncthreads();                     // all threads done with bufs i-2, i-1
        if (tid == 0) {
            if (i + 4 < 32) stage(i + 4);
            if (i + 5 < 32) stage(i + 5);
        }
        compute(s0 + b0 * STAGEB);
        compute(s0 + b1 * STAGEB);
    }

    const int g = lane >> 2, t = lane & 3;
    #pragma unroll
    for (int mt = 0; mt < 4; mt++) {
        const int r0 = row0 + wr + mt * 16 + g;
        #pragma unroll
        for (int nt = 0; nt < 8; nt++) {
            const int c = col0 + wc + nt * 8 + 2 * t;
            const float qs = (c < q_cols) ? QSCALE : 1.f;
            const float b0v = bias[c], b1v = bias[c + 1];
            if (half_out) {
                __half* Ch = (__half*)Cout;
                *reinterpret_cast<__half2*>(&Ch[(size_t)r0 * N + c]) =
                    __floats2half2_rn((acc[mt][nt][0] + b0v) * qs, (acc[mt][nt][1] + b1v) * qs);
                *reinterpret_cast<__half2*>(&Ch[(size_t)(r0 + 8) * N + c]) =
                    __floats2half2_rn((acc[mt][nt][2] + b0v) * qs, (acc[mt][nt][3] + b1v) * qs);
            } else {
                float* Cf = (float*)Cout;
                *reinterpret_cast<float2*>(&Cf[(size_t)r0 * N + c]) =
                    make_float2(acc[mt][nt][0] + b0v, acc[mt][nt][1] + b1v);
                *reinterpret_cast<float2*>(&Cf[(size_t)(r0 + 8) * N + c]) =
                    make_float2(acc[mt][nt][2] + b0v, acc[mt][nt][3] + b1v);
            }
        }
    }
}

// ---------------------------------------------------------------------------
// Causal flash attention (proven structure): causal pairing, 4 warps,
// ldmx4 K / ldmx4t V frags, register P, log2 softmax, 3-stage cp.async ring.
// Epilogue writes proj's A operand in PACKED swizzled layout (g_attnP).
// ---------------------------------------------------------------------------
#define LDS_ 72
#define AT_QBYTES   (128 * LDS_ * 2)
#define AT_KVSTAGE  (2 * 64 * LDS_ * 2)
#define AT_VOFF     (64 * LDS_ * 2)
#define AT_SMEM     (AT_QBYTES + 3 * AT_KVSTAGE)   // 73728 B -> 2 CTA/SM

__global__ __launch_bounds__(128, 1) void attn_f16_kernel(int T)
{
    extern __shared__ char smraw[];
    const uint32_t sQ  = smem_u32(smraw);
    const uint32_t sKV = sQ + AT_QBYTES;

    const int pair = blockIdx.x;
    const int nq   = gridDim.x * 2;
    const int h    = blockIdx.y;
    const int b    = blockIdx.z;
    const int tid  = threadIdx.x;
    const int lane = tid & 31;
    const int warp = tid >> 5;
    const int g = lane >> 2;
    const int t = lane & 3;

    const int rb = warp * 32;
    const size_t rowstride = 3 * DIMC;

    const int f_row = lane & 15, f_k = (lane >> 4) << 3;
    const int v_row = ((lane >> 3) & 1) * 8 + (lane & 7);
    const int v_col = (lane >> 4) * 8;
    const uint32_t koff = (f_row * LDS_ + f_k) * 2;

    const __half* pK = g_qkv + (size_t)(b * T + (tid >> 3)) * rowstride + DIMC + h * HDIM + (tid & 7) * 8;
    const __half* pV = pK + DIMC;
    const uint32_t dKV = ((tid >> 3) * LDS_ + (tid & 7) * 8) * 2;

    __half* Qs = (__half*)smraw;

    auto stageKV = [&](int kv0, uint32_t base) {
        #pragma unroll
        for (int it = 0; it < 4; it++)
            CP_ASYNC16(base + dKV + it * (16 * LDS_ * 2),
                       pK + (size_t)(kv0 + it * 16) * rowstride);
        #pragma unroll
        for (int it = 0; it < 4; it++)
            CP_ASYNC16(base + AT_VOFF + dKV + it * (16 * LDS_ * 2),
                       pV + (size_t)(kv0 + it * 16) * rowstride);
    };

    for (int sub = 0; sub < 2; sub++) {
        const int qt = sub ? (nq - 1 - pair) : pair;
        const int q0 = qt * 128;

        __syncthreads();

        uint32_t cb0 = sKV, cb1 = sKV + AT_KVSTAGE, cb2 = sKV + 2 * AT_KVSTAGE;
        const int nkv = 2 * qt + 2;

        stageKV(0,  cb0); CP_COMMIT();
        stageKV(64, cb1); CP_COMMIT();

        #pragma unroll
        for (int it = 0; it < 8; it++) {
            const int idx = it * 128 + tid;
            const int r = idx >> 3, c = idx & 7;
            *reinterpret_cast<uint4*>(&Qs[r * LDS_ + c * 8]) =
                *reinterpret_cast<const uint4*>(
                    &g_qkv[(size_t)(b * T + q0 + r) * rowstride + h * HDIM + c * 8]);
        }
        __syncthreads();

        unsigned qf[4][2][4];
        #pragma unroll
        for (int ks = 0; ks < 4; ks++)
            #pragma unroll
            for (int mt = 0; mt < 2; mt++)
                ldmx4(qf[ks][mt], sQ + ((rb + mt * 16 + f_row) * LDS_ + ks * 16 + f_k) * 2);

        float o[2][8][4];
        #pragma unroll
        for (int mt = 0; mt < 2; mt++)
            #pragma unroll
            for (int nt = 0; nt < 8; nt++)
                #pragma unroll
                for (int i = 0; i < 4; i++) o[mt][nt][i] = 0.f;

        float mx[2][2], ls[2][2];
        #pragma unroll
        for (int mt = 0; mt < 2; mt++) { mx[mt][0] = mx[mt][1] = -1e30f; ls[mt][0] = ls[mt][1] = 0.f; }

        for (int kt_i = 0; kt_i < nkv; kt_i++) {
            CP_WAIT(1);
            __syncthreads();
            if (kt_i + 2 < nkv) stageKV((kt_i + 2) * 64, cb2);
            CP_COMMIT();

            const uint32_t kb = cb0;
            const uint32_t vb = cb0 + AT_VOFF;
            const int kv0 = kt_i * 64;

            float s[2][8][4];
            #pragma unroll
            for (int mt = 0; mt < 2; mt++)
                #pragma unroll
                for (int nt = 0; nt < 8; nt++)
                    #pragma unroll
                    for (int i = 0; i < 4; i++) s[mt][nt][i] = 0.f;

            #pragma unroll
            for (int ks = 0; ks < 4; ks++) {
                #pragma unroll
                for (int ntp = 0; ntp < 4; ntp++) {
                    unsigned kf[4];
                    ldmx4(kf, kb + koff + ks * 32 + ntp * (16 * LDS_ * 2));
                    #pragma unroll
                    for (int mt = 0; mt < 2; mt++) {
                        mma_f16(s[mt][2 * ntp],     qf[ks][mt], kf[0], kf[2]);
                        mma_f16(s[mt][2 * ntp + 1], qf[ks][mt], kf[1], kf[3]);
                    }
                }
            }

            const bool do_mask = (kt_i >= 2 * qt);
            #pragma unroll
            for (int mt = 0; mt < 2; mt++) {
                const int rg0 = q0 + rb + mt * 16 + g;
                const int rg1 = rg0 + 8;
                float m0loc = -1e30f, m1loc = -1e30f;
                #pragma unroll
                for (int nt = 0; nt < 8; nt++) {
                    const int j = kv0 + nt * 8 + 2 * t;
                    if (do_mask) {
                        #pragma unroll
                        for (int c = 0; c < 2; c++) {
                            if (j + c > rg0) s[mt][nt][c]     = -1e30f;
                            if (j + c > rg1) s[mt][nt][c + 2] = -1e30f;
                        }
                    }
                    m0loc = fmaxf(m0loc, fmaxf(s[mt][nt][0], s[mt][nt][1]));
                    m1loc = fmaxf(m1loc, fmaxf(s[mt][nt][2], s[mt][nt][3]));
                }
                m0loc = fmaxf(m0loc, __shfl_xor_sync(0xffffffffu, m0loc, 1));
                m0loc = fmaxf(m0loc, __shfl_xor_sync(0xffffffffu, m0loc, 2));
                m1loc = fmaxf(m1loc, __shfl_xor_sync(0xffffffffu, m1loc, 1));
                m1loc = fmaxf(m1loc, __shfl_xor_sync(0xffffffffu, m1loc, 2));

                const float m0n = fmaxf(mx[mt][0], m0loc);
                const float m1n = fmaxf(mx[mt][1], m1loc);
                const float corr0 = ex2f(mx[mt][0] - m0n);
                const float corr1 = ex2f(mx[mt][1] - m1n);

                float l0loc = 0.f, l1loc = 0.f;
                #pragma unroll
                for (int nt = 0; nt < 8; nt++) {
                    float p00 = ex2f(s[mt][nt][0] - m0n);
                    float p01 = ex2f(s[mt][nt][1] - m0n);
                    float p10 = ex2f(s[mt][nt][2] - m1n);
                    float p11 = ex2f(s[mt][nt][3] - m1n);
                    l0loc += p00 + p01;
                    l1loc += p10 + p11;
                    s[mt][nt][0] = p00; s[mt][nt][1] = p01;
                    s[mt][nt][2] = p10; s[mt][nt][3] = p11;
                }
                l0loc += __shfl_xor_sync(0xffffffffu, l0loc, 1);
                l0loc += __shfl_xor_sync(0xffffffffu, l0loc, 2);
                l1loc += __shfl_xor_sync(0xffffffffu, l1loc, 1);
                l1loc += __shfl_xor_sync(0xffffffffu, l1loc, 2);

                ls[mt][0] = ls[mt][0] * corr0 + l0loc;
                ls[mt][1] = ls[mt][1] * corr1 + l1loc;
                mx[mt][0] = m0n; mx[mt][1] = m1n;

                #pragma unroll
                for (int nt = 0; nt < 8; nt++) {
                    o[mt][nt][0] *= corr0; o[mt][nt][1] *= corr0;
                    o[mt][nt][2] *= corr1; o[mt][nt][3] *= corr1;
                }
            }

            #pragma unroll
            for (int ks = 0; ks < 4; ks++) {
                unsigned pa[2][4];
                #pragma unroll
                for (int mt = 0; mt < 2; mt++) {
                    pa[mt][0] = pack2(s[mt][2 * ks][0],     s[mt][2 * ks][1]);
                    pa[mt][1] = pack2(s[mt][2 * ks][2],     s[mt][2 * ks][3]);
                    pa[mt][2] = pack2(s[mt][2 * ks + 1][0], s[mt][2 * ks + 1][1]);
                    pa[mt][3] = pack2(s[mt][2 * ks + 1][2], s[mt][2 * ks + 1][3]);
                }
                #pragma unroll
                for (int ntp = 0; ntp < 4; ntp++) {
                    unsigned vf[4];
                    ldmx4t(vf, vb + ((ks * 16 + v_row) * LDS_ + ntp * 16 + v_col) * 2);
                    #pragma unroll
                    for (int mt = 0; mt < 2; mt++) {
                        mma_f16(o[mt][2 * ntp],     pa[mt], vf[0], vf[1]);
                        mma_f16(o[mt][2 * ntp + 1], pa[mt], vf[2], vf[3]);
                    }
                }
            }

            uint32_t t0 = cb0; cb0 = cb1; cb1 = cb2; cb2 = t0;
        }

        CP_WAIT(0);

        // ---- epilogue: write packed+swizzled A tiles for the proj GEMM
        const int mbA = (b * T + q0) >> 7;
        #pragma unroll
        for (int mt = 0; mt < 2; mt++) {
            const float inv0 = 1.f / ls[mt][0];
            const float inv1 = 1.f / ls[mt][1];
            const int r0 = rb + mt * 16 + g;
            const int r1 = r0 + 8;
            const uint32_t xv0 = ((r0 >> 1) & 3) << 4;
            const uint32_t xv1 = ((r1 >> 1) & 3) << 4;
            #pragma unroll
            for (int nt = 0; nt < 8; nt++) {
                const int d = nt * 8 + 2 * t;
                const int kcA = (h << 1) + (d >> 5);
                const uint32_t cbyte = (d & 31) * 2;
                char* bp = (char*)g_attnP + (size_t)(mbA * 32 + kcA) * ABLKB;
                *reinterpret_cast<__half2*>(bp + r0 * 64 + (cbyte ^ xv0)) =
                    __floats2half2_rn(o[mt][nt][0] * inv0, o[mt][nt][1] * inv0);
                *reinterpret_cast<__half2*>(bp + r1 * 64 + (cbyte ^ xv1)) =
                    __floats2half2_rn(o[mt][nt][2] * inv1, o[mt][nt][3] * inv1);
            }
        }
    }
}

// ---------------------------------------------------------------------------
// Launch
// ---------------------------------------------------------------------------
extern "C" void kernel_launch(void* const* d_in, const int* in_sizes, int n_in,
                              void* d_out, int out_size)
{
    const float* x      = (const float*)d_in[0];
    const float* W_qkv  = (const float*)d_in[1];
    const float* b_qkv  = (const float*)d_in[2];
    const float* W_proj = (const float*)d_in[3];
    const float* b_proj = (const float*)d_in[4];
    float* out = (float*)d_out;

    const int M = in_sizes[0] / DIMC;   // 4096
    const int T = M / BATCH;            // 2048

    __half *xA, *wqkvB, *wprojB, *qkv, *attnP;
    cudaGetSymbolAddress((void**)&xA,     g_xA);
    cudaGetSymbolAddress((void**)&wqkvB,  g_wqkvB);
    cudaGetSymbolAddress((void**)&wprojB, g_wprojB);
    cudaGetSymbolAddress((void**)&qkv,    g_qkv);
    cudaGetSymbolAddress((void**)&attnP,  g_attnP);

    static cudaStream_t s1 = nullptr, s2 = nullptr;
    static cudaEvent_t evRoot, evQkvW, evProjW;
    if (!s1) {
        cudaStreamCreateWithFlags(&s1, cudaStreamNonBlocking);
        cudaStreamCreateWithFlags(&s2, cudaStreamNonBlocking);
        cudaEventCreateWithFlags(&evRoot,  cudaEventDisableTiming);
        cudaEventCreateWithFlags(&evQkvW,  cudaEventDisableTiming);
        cudaEventCreateWithFlags(&evProjW, cudaEventDisableTiming);
        cudaFuncSetAttribute(gemm_bulk_kernel,
                             cudaFuncAttributeMaxDynamicSharedMemorySize, G_SMEM);
        cudaFuncSetAttribute(attn_f16_kernel,
                             cudaFuncAttributeMaxDynamicSharedMemorySize, AT_SMEM);
    }

    // fork packers
    cudaEventRecord(evRoot, 0);
    cudaStreamWaitEvent(s1, evRoot, 0);
    cudaStreamWaitEvent(s2, evRoot, 0);

    xpack_kernel<<<dim3(32, M / 128), 256>>>(x);                     // main stream
    wpack_kernel<<<dim3(12, 32), 256, 0, s1>>>(W_qkv, wqkvB, 3 * DIMC);
    wpack_kernel<<<dim3(4, 32),  256, 0, s2>>>(W_proj, wprojB, DIMC);
    cudaEventRecord(evQkvW,  s1);
    cudaEventRecord(evProjW, s2);

    // 1) QKV = x @ W_qkv + b_qkv  (fp16 out, Q pre-scaled)
    cudaStreamWaitEvent(0, evQkvW, 0);
    gemm_bulk_kernel<<<dim3(12, M / 128), 256, G_SMEM>>>(
        xA, wqkvB, b_qkv, qkv, 3 * DIMC, 1, DIMC);

    // 2) causal attention: paired q-tiles, uniform work, single wave
    attn_f16_kernel<<<dim3(T / 256, NHEAD, BATCH), 128, AT_SMEM>>>(T);

    // 3) out = attnP @ W_proj + b_proj  (fp32 out)
    cudaStreamWaitEvent(0, evProjW, 0);
    gemm_bulk_kernel<<<dim3(4, M / 128), 256, G_SMEM>>>(
        attnP, wprojB, b_proj, out, DIMC, 0, 0);
}

// round 17
// speedup vs baseline: 1.0202x; 1.0202x over previous
#include <cuda_runtime.h>
#include <cuda_fp16.h>
#include <cstdint>

#define DIMC   1024
#define NHEAD  16
#define HDIM   64
#define BATCH  2
#define MAXT   2048
#define MAXM   (BATCH * MAXT)

// q scale folded into Q at QKV epilogue: 1/sqrt(64) * log2(e)
#define QSCALE (0.125f * 1.4426950408889634f)

// Packed-tile geometry: A block = 128 rows x 32 k (fp16, 64B rows, swizzled) = 8KB
//                       B block = 128 rows x 32 k = 8KB  (128-col tiles)
#define ABLKB 8192
#define BBLKB 8192

// Scratch (__device__ globals; no cudaMalloc allowed). 128B-aligned for bulk DMA.
__device__ __align__(128) __half g_xA[(size_t)MAXM * DIMC];        // packed A (QKV)
__device__ __align__(128) __half g_wqkvB[(size_t)3 * DIMC * DIMC]; // packed B (QKV)
__device__ __align__(128) __half g_wprojB[(size_t)DIMC * DIMC];    // packed B (proj)
__device__ __align__(128) __half g_qkv[(size_t)MAXM * 3 * DIMC];   // row-major (attn in)
__device__ __align__(128) __half g_attnP[(size_t)MAXM * DIMC];     // packed A (proj)

// ---------------------------------------------------------------------------
// helpers
// ---------------------------------------------------------------------------
__device__ __forceinline__ uint32_t smem_u32(const void* p) {
    uint32_t a;
    asm("{ .reg .u64 t; cvta.to.shared.u64 t, %1; cvt.u32.u64 %0, t; }" : "=r"(a) : "l"(p));
    return a;
}

#define CP_ASYNC16(dst_u32, src_ptr) \
    asm volatile("cp.async.cg.shared.global [%0], [%1], 16;" \
                 :: "r"(dst_u32), "l"(src_ptr) : "memory")
#define CP_COMMIT()  asm volatile("cp.async.commit_group;" ::: "memory")
#define CP_WAIT(n)   asm volatile("cp.async.wait_group %0;" :: "n"(n) : "memory")

#define CP_BULK(dst_u32, src_ptr, nbytes, mbar_u32) \
    asm volatile("cp.async.bulk.shared::cluster.global.mbarrier::complete_tx::bytes " \
                 "[%0], [%1], %2, [%3];" \
                 :: "r"(dst_u32), "l"(src_ptr), "r"(nbytes), "r"(mbar_u32) : "memory")

#define MBARRIER_INIT(addr, cnt) \
    asm volatile("mbarrier.init.shared.b64 [%0], %1;" :: "r"(addr), "r"(cnt) : "memory")
#define MBARRIER_EXPECT_TX(addr, tx) \
    asm volatile("mbarrier.arrive.expect_tx.shared.b64 _, [%0], %1;" \
                 :: "r"(addr), "r"(tx) : "memory")
#define MBARRIER_WAIT_PARITY(addr, par) do {                                        \
    uint32_t _m = (addr), _p = (par), _d;                                           \
    asm volatile("{\n\t.reg .pred p;\n\t"                                           \
        "mbarrier.try_wait.parity.acquire.cta.shared::cta.b64 p, [%1], %2;\n\t"     \
        "selp.b32 %0, 1, 0, p;\n\t}" : "=r"(_d) : "r"(_m), "r"(_p) : "memory");     \
    if (!_d) {                                                                      \
        asm volatile("{\n\t.reg .pred P1;\n\tWL_%=:\n\t"                            \
            "mbarrier.try_wait.parity.acquire.cta.shared::cta.b64 P1, [%0], %1, 0x989680;\n\t" \
            "@P1 bra.uni WD_%=;\n\tbra.uni WL_%=;\n\tWD_%=:\n\t}"                   \
            :: "r"(_m), "r"(_p) : "memory");                                        \
    }                                                                               \
} while (0)

__device__ __forceinline__ void mma_f16(float* d, const unsigned* a,
                                        unsigned b0, unsigned b1) {
    asm volatile(
        "mma.sync.aligned.m16n8k16.row.col.f32.f16.f16.f32 "
        "{%0,%1,%2,%3}, {%4,%5,%6,%7}, {%8,%9}, {%0,%1,%2,%3};\n"
        : "+f"(d[0]), "+f"(d[1]), "+f"(d[2]), "+f"(d[3])
        : "r"(a[0]), "r"(a[1]), "r"(a[2]), "r"(a[3]), "r"(b0), "r"(b1));
}

__device__ __forceinline__ void ldmx4(unsigned* r, uint32_t addr) {
    asm volatile("ldmatrix.sync.aligned.m8n8.x4.shared.b16 {%0,%1,%2,%3}, [%4];"
                 : "=r"(r[0]), "=r"(r[1]), "=r"(r[2]), "=r"(r[3]) : "r"(addr));
}
__device__ __forceinline__ void ldmx4t(unsigned* r, uint32_t addr) {
    asm volatile("ldmatrix.sync.aligned.m8n8.x4.trans.shared.b16 {%0,%1,%2,%3}, [%4];"
                 : "=r"(r[0]), "=r"(r[1]), "=r"(r[2]), "=r"(r[3]) : "r"(addr));
}

__device__ __forceinline__ unsigned pack2(float x, float y) {
    __half2 h = __floats2half2_rn(x, y);
    return *reinterpret_cast<unsigned*>(&h);
}
__device__ __forceinline__ float ex2f(float x) {
    float y;
    asm("ex2.approx.f32 %0, %1;" : "=f"(y) : "f"(x));
    return y;
}

// ---------------------------------------------------------------------------
// Packers: write (row, col) at row*64 + (col_bytes ^ xorv(row)),
// xorv(row) = ((row>>1)&3)<<4.
// ---------------------------------------------------------------------------
__global__ __launch_bounds__(256) void xpack_kernel(const float* __restrict__ x) {
    const int kc = blockIdx.x, mb = blockIdx.y;
    const int tid = threadIdx.x;
    const int r = tid >> 1, hf = tid & 1;
    const float* src = x + (size_t)(mb * 128 + r) * DIMC + kc * 32 + hf * 16;
    float4 v0 = *reinterpret_cast<const float4*>(src);
    float4 v1 = *reinterpret_cast<const float4*>(src + 4);
    float4 v2 = *reinterpret_cast<const float4*>(src + 8);
    float4 v3 = *reinterpret_cast<const float4*>(src + 12);
    uint4 u0 = make_uint4(pack2(v0.x, v0.y), pack2(v0.z, v0.w),
                          pack2(v1.x, v1.y), pack2(v1.z, v1.w));
    uint4 u1 = make_uint4(pack2(v2.x, v2.y), pack2(v2.z, v2.w),
                          pack2(v3.x, v3.y), pack2(v3.z, v3.w));
    const uint32_t xorv = ((r >> 1) & 3) << 4;
    char* dst = (char*)g_xA + (size_t)(mb * 32 + kc) * ABLKB + r * 64;
    *reinterpret_cast<uint4*>(dst + ((hf * 32)      ^ xorv)) = u0;
    *reinterpret_cast<uint4*>(dst + ((hf * 32 + 16) ^ xorv)) = u1;
}

// W fp32 [1024,N] -> packed B [nb128][kc][128x32 f16 swizzled], rows = n
__global__ __launch_bounds__(128) void wpack_kernel(const float* __restrict__ W,
                                                    __half* __restrict__ out, int N) {
    const int nb = blockIdx.x, kc = blockIdx.y;
    const int n = threadIdx.x;   // 0..127
    __half h[32];
    #pragma unroll
    for (int k = 0; k < 32; k++)
        h[k] = __float2half_rn(W[(size_t)(kc * 32 + k) * N + nb * 128 + n]);
    const uint32_t xorv = ((n >> 1) & 3) << 4;
    char* dst = (char*)out + (size_t)(nb * 32 + kc) * BBLKB + n * 64;
    const uint4* hu = reinterpret_cast<const uint4*>(h);
    #pragma unroll
    for (int u = 0; u < 4; u++)
        *reinterpret_cast<uint4*>(dst + ((u * 16) ^ xorv)) = hu[u];
}

// ---------------------------------------------------------------------------
// Bulk-DMA fp16 GEMM + bias: 128(M) x 128(N) CTA tile, 8 warps (32x64 warp
// tiles), BK=32, 6-buffer ring fed by cp.async.bulk + mbarrier.
// 2 CTAs/SM (<=128 regs, 98.4KB smem) — second CTA hides wait/ldsm bubbles.
// ---------------------------------------------------------------------------
#define STAGEB   (ABLKB + BBLKB)       // 16384
#define NBUF     6
#define MBAR_OFF (NBUF * STAGEB)       // 98304
#define G_SMEM   (MBAR_OFF + 64)       // 98368

__global__ __launch_bounds__(256, 2) void gemm_bulk_kernel(
    const __half* __restrict__ Apack, const __half* __restrict__ Bpack,
    const float* __restrict__ bias, void* __restrict__ Cout,
    int N, int half_out, int q_cols)
{
    extern __shared__ char smraw[];
    const uint32_t s0 = smem_u32(smraw);

    const int tid  = threadIdx.x;
    const int lane = tid & 31;
    const int warp = tid >> 5;
    const int wr = (warp >> 1) * 32;     // 0,32,64,96
    const int wc = (warp & 1) * 64;      // 0,64
    const int mb = blockIdx.y, nb = blockIdx.x;
    const int row0 = mb * 128, col0 = nb * 128;

    if (tid == 0) {
        #pragma unroll
        for (int s = 0; s < NBUF; s++) MBARRIER_INIT(s0 + MBAR_OFF + 8 * s, 1);
    }
    __syncthreads();

    float acc[2][8][4];
    #pragma unroll
    for (int mt = 0; mt < 2; mt++)
        #pragma unroll
        for (int nt = 0; nt < 8; nt++)
            #pragma unroll
            for (int i = 0; i < 4; i++) acc[mt][nt][i] = 0.f;

    const char* Abase = (const char*)Apack + (size_t)mb * 32 * ABLKB;
    const char* Bbase = (const char*)Bpack + (size_t)nb * 32 * BBLKB;

    auto stage = [&](int kc, int buf) {
        const uint32_t mbar = s0 + MBAR_OFF + 8 * buf;
        const uint32_t dst  = s0 + buf * STAGEB;
        MBARRIER_EXPECT_TX(mbar, STAGEB);
        CP_BULK(dst,         Abase + (size_t)kc * ABLKB, ABLKB, mbar);
        CP_BULK(dst + ABLKB, Bbase + (size_t)kc * BBLKB, BBLKB, mbar);
    };

    // fragment addressing
    const int f_row = lane & 15;
    const uint32_t cb = (lane >> 4) << 4;   // 0 or 16 bytes
    uint32_t rbA[2], xvA[2], rbB[4], xvB[4];
    #pragma unroll
    for (int i = 0; i < 2; i++) {
        const int rA = wr + i * 16 + f_row;
        rbA[i] = rA * 64;          xvA[i] = ((rA >> 1) & 3) << 4;
    }
    #pragma unroll
    for (int i = 0; i < 4; i++) {
        const int rB = wc + i * 16 + f_row;
        rbB[i] = ABLKB + rB * 64;  xvB[i] = ((rB >> 1) & 3) << 4;
    }

    auto compute = [&](uint32_t base) {
        #pragma unroll
        for (int ks = 0; ks < 2; ks++) {
            const uint32_t col = ks * 32 + cb;
            unsigned af[2][4], bf[4][4];
            #pragma unroll
            for (int mt = 0; mt < 2; mt++)
                ldmx4(af[mt], base + rbA[mt] + (col ^ xvA[mt]));
            #pragma unroll
            for (int ntp = 0; ntp < 4; ntp++)
                ldmx4(bf[ntp], base + rbB[ntp] + (col ^ xvB[ntp]));
            #pragma unroll
            for (int mt = 0; mt < 2; mt++)
                #pragma unroll
                for (int ntp = 0; ntp < 4; ntp++) {
                    mma_f16(acc[mt][2 * ntp],     af[mt], bf[ntp][0], bf[ntp][2]);
                    mma_f16(acc[mt][2 * ntp + 1], af[mt], bf[ntp][1], bf[ntp][3]);
                }
        }
    };

    if (tid == 0) { stage(0, 0); stage(1, 1); stage(2, 2); stage(3, 3); }

    // add/wrap ring counters (no % in the loop)
    int b0 = 0, b1 = 1, bs0 = 4, bs1 = 5;
    int par[NBUF] = {0, 0, 0, 0, 0, 0};
    for (int i = 0; i < 32; i += 2) {
        MBARRIER_WAIT_PARITY(s0 + MBAR_OFF + 8 * b0, par[b0]); par[b0] ^= 1;
        MBARRIER_WAIT_PARITY(s0 + MBAR_OFF + 8 * b1, par[b1]); par[b1] ^= 1;
        __syncthreads();                     // all threads done with bufs i-2, i-1
        if (tid == 0) {
            if (i + 4 < 32) stage(i + 4, bs0);
            if (i + 5 < 32) stage(i + 5, bs1);
        }
        compute(s0 + b0 * STAGEB);
        compute(s0 + b1 * STAGEB);
        b0 += 2;  if (b0 >= NBUF) b0 -= NBUF;
        b1 += 2;  if (b1 >= NBUF) b1 -= NBUF;
        bs0 += 2; if (bs0 >= NBUF) bs0 -= NBUF;
        bs1 += 2; if (bs1 >= NBUF) bs1 -= NBUF;
    }

    const int g = lane >> 2, t = lane & 3;
    #pragma unroll
    for (int mt = 0; mt < 2; mt++) {
        const int r0 = row0 + wr + mt * 16 + g;
        #pragma unroll
        for (int nt = 0; nt < 8; nt++) {
            const int c = col0 + wc + nt * 8 + 2 * t;
            const float qs = (c < q_cols) ? QSCALE : 1.f;
            const float b0v = bias[c], b1v = bias[c + 1];
            if (half_out) {
                __half* Ch = (__half*)Cout;
                *reinterpret_cast<__half2*>(&Ch[(size_t)r0 * N + c]) =
                    __floats2half2_rn((acc[mt][nt][0] + b0v) * qs, (acc[mt][nt][1] + b1v) * qs);
                *reinterpret_cast<__half2*>(&Ch[(size_t)(r0 + 8) * N + c]) =
                    __floats2half2_rn((acc[mt][nt][2] + b0v) * qs, (acc[mt][nt][3] + b1v) * qs);
            } else {
                float* Cf = (float*)Cout;
                *reinterpret_cast<float2*>(&Cf[(size_t)r0 * N + c]) =
                    make_float2(acc[mt][nt][0] + b0v, acc[mt][nt][1] + b1v);
                *reinterpret_cast<float2*>(&Cf[(size_t)(r0 + 8) * N + c]) =
                    make_float2(acc[mt][nt][2] + b0v, acc[mt][nt][3] + b1v);
            }
        }
    }
}

// ---------------------------------------------------------------------------
// Causal flash attention (proven, unchanged): causal pairing, 4 warps,
// ldmx4 K / ldmx4t V frags, register P, log2 softmax, 3-stage cp.async ring.
// Epilogue writes proj's A operand in PACKED swizzled layout (g_attnP).
// ---------------------------------------------------------------------------
#define LDS_ 72
#define AT_QBYTES   (128 * LDS_ * 2)
#define AT_KVSTAGE  (2 * 64 * LDS_ * 2)
#define AT_VOFF     (64 * LDS_ * 2)
#define AT_SMEM     (AT_QBYTES + 3 * AT_KVSTAGE)   // 73728 B -> 2 CTA/SM

__global__ __launch_bounds__(128, 1) void attn_f16_kernel(int T)
{
    extern __shared__ char smraw[];
    const uint32_t sQ  = smem_u32(smraw);
    const uint32_t sKV = sQ + AT_QBYTES;

    const int pair = blockIdx.x;
    const int nq   = gridDim.x * 2;
    const int h    = blockIdx.y;
    const int b    = blockIdx.z;
    const int tid  = threadIdx.x;
    const int lane = tid & 31;
    const int warp = tid >> 5;
    const int g = lane >> 2;
    const int t = lane & 3;

    const int rb = warp * 32;
    const size_t rowstride = 3 * DIMC;

    const int f_row = lane & 15, f_k = (lane >> 4) << 3;
    const int v_row = ((lane >> 3) & 1) * 8 + (lane & 7);
    const int v_col = (lane >> 4) * 8;
    const uint32_t koff = (f_row * LDS_ + f_k) * 2;

    const __half* pK = g_qkv + (size_t)(b * T + (tid >> 3)) * rowstride + DIMC + h * HDIM + (tid & 7) * 8;
    const __half* pV = pK + DIMC;
    const uint32_t dKV = ((tid >> 3) * LDS_ + (tid & 7) * 8) * 2;

    __half* Qs = (__half*)smraw;

    auto stageKV = [&](int kv0, uint32_t base) {
        #pragma unroll
        for (int it = 0; it < 4; it++)
            CP_ASYNC16(base + dKV + it * (16 * LDS_ * 2),
                       pK + (size_t)(kv0 + it * 16) * rowstride);
        #pragma unroll
        for (int it = 0; it < 4; it++)
            CP_ASYNC16(base + AT_VOFF + dKV + it * (16 * LDS_ * 2),
                       pV + (size_t)(kv0 + it * 16) * rowstride);
    };

    for (int sub = 0; sub < 2; sub++) {
        const int qt = sub ? (nq - 1 - pair) : pair;
        const int q0 = qt * 128;

        __syncthreads();

        uint32_t cb0 = sKV, cb1 = sKV + AT_KVSTAGE, cb2 = sKV + 2 * AT_KVSTAGE;
        const int nkv = 2 * qt + 2;

        stageKV(0,  cb0); CP_COMMIT();
        stageKV(64, cb1); CP_COMMIT();

        #pragma unroll
        for (int it = 0; it < 8; it++) {
            const int idx = it * 128 + tid;
            const int r = idx >> 3, c = idx & 7;
            *reinterpret_cast<uint4*>(&Qs[r * LDS_ + c * 8]) =
                *reinterpret_cast<const uint4*>(
                    &g_qkv[(size_t)(b * T + q0 + r) * rowstride + h * HDIM + c * 8]);
        }
        __syncthreads();

        unsigned qf[4][2][4];
        #pragma unroll
        for (int ks = 0; ks < 4; ks++)
            #pragma unroll
            for (int mt = 0; mt < 2; mt++)
                ldmx4(qf[ks][mt], sQ + ((rb + mt * 16 + f_row) * LDS_ + ks * 16 + f_k) * 2);

        float o[2][8][4];
        #pragma unroll
        for (int mt = 0; mt < 2; mt++)
            #pragma unroll
            for (int nt = 0; nt < 8; nt++)
                #pragma unroll
                for (int i = 0; i < 4; i++) o[mt][nt][i] = 0.f;

        float mx[2][2], ls[2][2];
        #pragma unroll
        for (int mt = 0; mt < 2; mt++) { mx[mt][0] = mx[mt][1] = -1e30f; ls[mt][0] = ls[mt][1] = 0.f; }

        for (int kt_i = 0; kt_i < nkv; kt_i++) {
            CP_WAIT(1);
            __syncthreads();
            if (kt_i + 2 < nkv) stageKV((kt_i + 2) * 64, cb2);
            CP_COMMIT();

            const uint32_t kb = cb0;
            const uint32_t vb = cb0 + AT_VOFF;
            const int kv0 = kt_i * 64;

            float s[2][8][4];
            #pragma unroll
            for (int mt = 0; mt < 2; mt++)
                #pragma unroll
                for (int nt = 0; nt < 8; nt++)
                    #pragma unroll
                    for (int i = 0; i < 4; i++) s[mt][nt][i] = 0.f;

            #pragma unroll
            for (int ks = 0; ks < 4; ks++) {
                #pragma unroll
                for (int ntp = 0; ntp < 4; ntp++) {
                    unsigned kf[4];
                    ldmx4(kf, kb + koff + ks * 32 + ntp * (16 * LDS_ * 2));
                    #pragma unroll
                    for (int mt = 0; mt < 2; mt++) {
                        mma_f16(s[mt][2 * ntp],     qf[ks][mt], kf[0], kf[2]);
                        mma_f16(s[mt][2 * ntp + 1], qf[ks][mt], kf[1], kf[3]);
                    }
                }
            }

            const bool do_mask = (kt_i >= 2 * qt);
            #pragma unroll
            for (int mt = 0; mt < 2; mt++) {
                const int rg0 = q0 + rb + mt * 16 + g;
                const int rg1 = rg0 + 8;
                float m0loc = -1e30f, m1loc = -1e30f;
                #pragma unroll
                for (int nt = 0; nt < 8; nt++) {
                    const int j = kv0 + nt * 8 + 2 * t;
                    if (do_mask) {
                        #pragma unroll
                        for (int c = 0; c < 2; c++) {
                            if (j + c > rg0) s[mt][nt][c]     = -1e30f;
                            if (j + c > rg1) s[mt][nt][c + 2] = -1e30f;
                        }
                    }
                    m0loc = fmaxf(m0loc, fmaxf(s[mt][nt][0], s[mt][nt][1]));
                    m1loc = fmaxf(m1loc, fmaxf(s[mt][nt][2], s[mt][nt][3]));
                }
                m0loc = fmaxf(m0loc, __shfl_xor_sync(0xffffffffu, m0loc, 1));
                m0loc = fmaxf(m0loc, __shfl_xor_sync(0xffffffffu, m0loc, 2));
                m1loc = fmaxf(m1loc, __shfl_xor_sync(0xffffffffu, m1loc, 1));
                m1loc = fmaxf(m1loc, __shfl_xor_sync(0xffffffffu, m1loc, 2));

                const float m0n = fmaxf(mx[mt][0], m0loc);
                const float m1n = fmaxf(mx[mt][1], m1loc);
                const float corr0 = ex2f(mx[mt][0] - m0n);
                const float corr1 = ex2f(mx[mt][1] - m1n);

                float l0loc = 0.f, l1loc = 0.f;
                #pragma unroll
                for (int nt = 0; nt < 8; nt++) {
                    float p00 = ex2f(s[mt][nt][0] - m0n);
                    float p01 = ex2f(s[mt][nt][1] - m0n);
                    float p10 = ex2f(s[mt][nt][2] - m1n);
                    float p11 = ex2f(s[mt][nt][3] - m1n);
                    l0loc += p00 + p01;
                    l1loc += p10 + p11;
                    s[mt][nt][0] = p00; s[mt][nt][1] = p01;
                    s[mt][nt][2] = p10; s[mt][nt][3] = p11;
                }
                l0loc += __shfl_xor_sync(0xffffffffu, l0loc, 1);
                l0loc += __shfl_xor_sync(0xffffffffu, l0loc, 2);
                l1loc += __shfl_xor_sync(0xffffffffu, l1loc, 1);
                l1loc += __shfl_xor_sync(0xffffffffu, l1loc, 2);

                ls[mt][0] = ls[mt][0] * corr0 + l0loc;
                ls[mt][1] = ls[mt][1] * corr1 + l1loc;
                mx[mt][0] = m0n; mx[mt][1] = m1n;

                #pragma unroll
                for (int nt = 0; nt < 8; nt++) {
                    o[mt][nt][0] *= corr0; o[mt][nt][1] *= corr0;
                    o[mt][nt][2] *= corr1; o[mt][nt][3] *= corr1;
                }
            }

            #pragma unroll
            for (int ks = 0; ks < 4; ks++) {
                unsigned pa[2][4];
                #pragma unroll
                for (int mt = 0; mt < 2; mt++) {
                    pa[mt][0] = pack2(s[mt][2 * ks][0],     s[mt][2 * ks][1]);
                    pa[mt][1] = pack2(s[mt][2 * ks][2],     s[mt][2 * ks][3]);
                    pa[mt][2] = pack2(s[mt][2 * ks + 1][0], s[mt][2 * ks + 1][1]);
                    pa[mt][3] = pack2(s[mt][2 * ks + 1][2], s[mt][2 * ks + 1][3]);
                }
                #pragma unroll
                for (int ntp = 0; ntp < 4; ntp++) {
                    unsigned vf[4];
                    ldmx4t(vf, vb + ((ks * 16 + v_row) * LDS_ + ntp * 16 + v_col) * 2);
                    #pragma unroll
                    for (int mt = 0; mt < 2; mt++) {
                        mma_f16(o[mt][2 * ntp],     pa[mt], vf[0], vf[1]);
                        mma_f16(o[mt][2 * ntp + 1], pa[mt], vf[2], vf[3]);
                    }
                }
            }

            uint32_t t0 = cb0; cb0 = cb1; cb1 = cb2; cb2 = t0;
        }

        CP_WAIT(0);

        // ---- epilogue: write packed+swizzled A tiles for the proj GEMM
        const int mbA = (b * T + q0) >> 7;
        #pragma unroll
        for (int mt = 0; mt < 2; mt++) {
            const float inv0 = 1.f / ls[mt][0];
            const float inv1 = 1.f / ls[mt][1];
            const int r0 = rb + mt * 16 + g;
            const int r1 = r0 + 8;
            const uint32_t xv0 = ((r0 >> 1) & 3) << 4;
            const uint32_t xv1 = ((r1 >> 1) & 3) << 4;
            #pragma unroll
            for (int nt = 0; nt < 8; nt++) {
                const int d = nt * 8 + 2 * t;
                const int kcA = (h << 1) + (d >> 5);
                const uint32_t cbyte = (d & 31) * 2;
                char* bp = (char*)g_attnP + (size_t)(mbA * 32 + kcA) * ABLKB;
                *reinterpret_cast<__half2*>(bp + r0 * 64 + (cbyte ^ xv0)) =
                    __floats2half2_rn(o[mt][nt][0] * inv0, o[mt][nt][1] * inv0);
                *reinterpret_cast<__half2*>(bp + r1 * 64 + (cbyte ^ xv1)) =
                    __floats2half2_rn(o[mt][nt][2] * inv1, o[mt][nt][3] * inv1);
            }
        }
    }
}

// ---------------------------------------------------------------------------
// Launch
// ---------------------------------------------------------------------------
extern "C" void kernel_launch(void* const* d_in, const int* in_sizes, int n_in,
                              void* d_out, int out_size)
{
    const float* x      = (const float*)d_in[0];
    const float* W_qkv  = (const float*)d_in[1];
    const float* b_qkv  = (const float*)d_in[2];
    const float* W_proj = (const float*)d_in[3];
    const float* b_proj = (const float*)d_in[4];
    float* out = (float*)d_out;

    const int M = in_sizes[0] / DIMC;   // 4096
    const int T = M / BATCH;            // 2048

    __half *xA, *wqkvB, *wprojB, *qkv, *attnP;
    cudaGetSymbolAddress((void**)&xA,     g_xA);
    cudaGetSymbolAddress((void**)&wqkvB,  g_wqkvB);
    cudaGetSymbolAddress((void**)&wprojB, g_wprojB);
    cudaGetSymbolAddress((void**)&qkv,    g_qkv);
    cudaGetSymbolAddress((void**)&attnP,  g_attnP);

    static cudaStream_t s1 = nullptr, s2 = nullptr;
    static cudaEvent_t evRoot, evQkvW, evProjW;
    if (!s1) {
        cudaStreamCreateWithFlags(&s1, cudaStreamNonBlocking);
        cudaStreamCreateWithFlags(&s2, cudaStreamNonBlocking);
        cudaEventCreateWithFlags(&evRoot,  cudaEventDisableTiming);
        cudaEventCreateWithFlags(&evQkvW,  cudaEventDisableTiming);
        cudaEventCreateWithFlags(&evProjW, cudaEventDisableTiming);
        cudaFuncSetAttribute(gemm_bulk_kernel,
                             cudaFuncAttributeMaxDynamicSharedMemorySize, G_SMEM);
        cudaFuncSetAttribute(attn_f16_kernel,
                             cudaFuncAttributeMaxDynamicSharedMemorySize, AT_SMEM);
    }

    // fork packers
    cudaEventRecord(evRoot, 0);
    cudaStreamWaitEvent(s1, evRoot, 0);
    cudaStreamWaitEvent(s2, evRoot, 0);

    xpack_kernel<<<dim3(32, M / 128), 256>>>(x);
    wpack_kernel<<<dim3(24, 32), 128, 0, s1>>>(W_qkv, wqkvB, 3 * DIMC);
    wpack_kernel<<<dim3(8, 32),  128, 0, s2>>>(W_proj, wprojB, DIMC);
    cudaEventRecord(evQkvW,  s1);
    cudaEventRecord(evProjW, s2);

    // 1) QKV = x @ W_qkv + b_qkv  (fp16 out, Q pre-scaled)
    cudaStreamWaitEvent(0, evQkvW, 0);
    gemm_bulk_kernel<<<dim3(24, M / 128), 256, G_SMEM>>>(
        xA, wqkvB, b_qkv, qkv, 3 * DIMC, 1, DIMC);

    // 2) causal attention: paired q-tiles, uniform work, single wave
    attn_f16_kernel<<<dim3(T / 256, NHEAD, BATCH), 128, AT_SMEM>>>(T);

    // 3) out = attnP @ W_proj + b_proj  (fp32 out)
    cudaStreamWaitEvent(0, evProjW, 0);
    gemm_bulk_kernel<<<dim3(8, M / 128), 256, G_SMEM>>>(
        attnP, wprojB, b_proj, out, DIMC, 0, 0);
}